// round 10
// baseline (speedup 1.0000x reference)
#include <cuda_runtime.h>

#define NIMG 8
#define NA   25200
#define NCLS 80
#define ROWL 85
#define DETN 300
#define CONF 0.96f
#define IOUT 0.45f
#define BCAP 128            // per-(img,class) bucket capacity (E~20, sigma~4.5)
#define KCAP 2048           // per-image kept capacity
#define NBUCK 4096
#define NANCH (NIMG * NA)   // 201600

typedef unsigned long long u64;

// ---------------- device scratch (zero-initialized at module load;
// consumers reset what they read, so every graph replay starts clean) ------
__device__ int g_ccount[NIMG * NCLS];
__device__ u64 g_bucket[NIMG * NCLS * BCAP];
__device__ int g_kcount[NIMG];
__device__ u64 g_kept[NIMG * KCAP];
__device__ int g_done[NIMG];

// ---------------- K1: extraction — one WARP per anchor (R6 proven shape:
// all 788*8=201600 warps resident chip-wide -> max outstanding lines)
__global__ __launch_bounds__(256) void k_extract(const float* __restrict__ pred) {
    int w = blockIdx.x * (blockDim.x >> 5) + (threadIdx.x >> 5);
    int lane = threadIdx.x & 31;
    if (w >= NANCH) return;                  // never taken (grid matches exactly)
    int img = w / NA;
    int a   = w - img * NA;
    const float* row = pred + (size_t)w * ROWL;

    float obj = 0.f;
    if (lane == 0) obj = __ldg(row + 4);
    obj = __shfl_sync(0xFFFFFFFFu, obj, 0);
    if (!(obj > CONF)) return;               // ~96% of warps exit here

    #pragma unroll
    for (int base = 0; base < 96; base += 32) {
        int c = base + lane;
        if (c < NCLS) {
            float s = __fmul_rn(__ldg(row + 5 + c), obj);
            if (s > CONF) {
                unsigned fi = (unsigned)(a * NCLS + c);
                u64 key = ((u64)__float_as_uint(s) << 32)
                          | (u64)(0xFFFFFFFFu - fi);
                int slot = atomicAdd(&g_ccount[img * NCLS + c], 1);
                if (slot < BCAP)
                    g_bucket[(size_t)(img * NCLS + c) * BCAP + slot] = key;
            }
        }
    }
}

// ---------------- K2: per-(img,class) NMS (8 warps/block, 10 blocks/image)
// + last-block-per-image runs the top-300 selection inline.
//
// shared overlay: NMS phase uses snb/skey/sarea/skeep; the selection phase
// (after all the block's NMS work and a __syncthreads) reuses the same
// buffer as hist/cand. 29,696 bytes static.
__global__ __launch_bounds__(256) void k_nms(const float* __restrict__ pred,
                                             float* __restrict__ out) {
    __shared__ __align__(16) char sbuf[29696];
    float4*        snbA   = (float4*)(sbuf);            // [8][BCAP] 16384 B
    u64*           skeyA  = (u64*)(sbuf + 16384);       // [8][BCAP]  8192 B
    float*         sareaA = (float*)(sbuf + 24576);     // [8][BCAP]  4096 B
    unsigned char* skeepA = (unsigned char*)(sbuf + 28672); // [8][BCAP] 1024 B
    // selection overlay
    int* hist = (int*)(sbuf);                           // [NBUCK]   16384 B
    u64* cand = (u64*)(sbuf + 16384);                   // [512]      4096 B
    __shared__ int warp_sum[8], warp_suf[8];
    __shared__ int sB, skc, s_last;

    int tid  = threadIdx.x;
    int ws   = tid >> 5;
    int lane = tid & 31;
    int ww   = blockIdx.x * 8 + ws;          // (img, cls) id
    int img  = blockIdx.x / 10;              // 10 blocks per image
    int cls  = ww - img * NCLS;

    u64*           skey  = skeyA  + ws * BCAP;
    float4*        snb   = snbA   + ws * BCAP;
    float*         sarea = sareaA + ws * BCAP;
    unsigned char* skeep = skeepA + ws * BCAP;

    // ---------- NMS for this warp's class (no early returns!) ----------
    int m = 0;
    if (lane == 0) {                         // single-owner read + reset
        m = g_ccount[ww];
        if (m > 0) g_ccount[ww] = 0;
    }
    m = __shfl_sync(0xFFFFFFFFu, m, 0);
    if (m > BCAP) m = BCAP;

    if (m > 0) {
        const u64* bucket = g_bucket + (size_t)ww * BCAP;
        for (int t = lane; t < BCAP; t += 32)
            skey[t] = (t < m) ? bucket[t] : 0ULL;
        __syncwarp();

        // bitonic sort desc over 128 unique keys (zeros sink to tail)
        for (int k = 2; k <= BCAP; k <<= 1) {
            for (int j = k >> 1; j > 0; j >>= 1) {
                for (int t = lane; t < BCAP; t += 32) {
                    int x = t ^ j;
                    if (x > t) {
                        u64 va = skey[t], vb = skey[x];
                        bool up = ((t & k) == 0);
                        if ((va < vb) == up) { skey[t] = vb; skey[x] = va; }
                    }
                }
                __syncwarp();
            }
        }

        // decode offset boxes + areas (exact reference fp expression order)
        float off = __fmul_rn((float)cls, 4.0f);
        for (int t = lane; t < m; t += 32) {
            unsigned fi = 0xFFFFFFFFu - (unsigned)(skey[t] & 0xFFFFFFFFull);
            int anchor = (int)(fi / NCLS);
            const float* r = pred + ((size_t)img * NA + anchor) * ROWL;
            float cx = __ldg(r), cy = __ldg(r + 1), w2 = __ldg(r + 2), h2 = __ldg(r + 3);
            float hw = __fmul_rn(0.5f, w2);
            float hv = __fmul_rn(0.5f, h2);
            float4 nb;
            nb.x = __fadd_rn(__fsub_rn(cx, hw), off);
            nb.y = __fadd_rn(__fsub_rn(cy, hv), off);
            nb.z = __fadd_rn(__fadd_rn(cx, hw), off);
            nb.w = __fadd_rn(__fadd_rn(cy, hv), off);
            snb[t]   = nb;
            sarea[t] = __fmul_rn(__fsub_rn(nb.z, nb.x), __fsub_rn(nb.w, nb.y));
            skeep[t] = 1;
        }
        __syncwarp();

        // greedy NMS in sorted order (== global sequential scan within class;
        // cross-class IoU is exactly 0 under the label*4 offset)
        for (int i = 0; i < m; i++) {
            if (skeep[i]) {
                float4 bi = snb[i];
                float  ai = sarea[i];
                for (int t = i + 1 + lane; t < m; t += 32) {
                    if (skeep[t]) {
                        float4 bt = snb[t];
                        float lx = fmaxf(bi.x, bt.x), ly = fmaxf(bi.y, bt.y);
                        float rx = fminf(bi.z, bt.z), ry = fminf(bi.w, bt.w);
                        float iw = fmaxf(__fsub_rn(rx, lx), 0.f);
                        float ih = fmaxf(__fsub_rn(ry, ly), 0.f);
                        float inter = __fmul_rn(iw, ih);
                        float den = __fadd_rn(
                            __fsub_rn(__fadd_rn(ai, sarea[t]), inter), 1e-9f);
                        if (__fdiv_rn(inter, den) > IOUT) skeep[t] = 0;
                    }
                }
            }
            __syncwarp();
        }

        // push kept keys to the per-image list (rank restored by key later)
        for (int base = 0; base < BCAP; base += 32) {
            int t = base + lane;
            bool k = (t < m) && skeep[t];
            unsigned bal = __ballot_sync(0xFFFFFFFFu, k);
            int cnt = __popc(bal);
            if (cnt) {
                int pos = 0;
                if (lane == 0) pos = atomicAdd(&g_kcount[img], cnt);
                pos = __shfl_sync(0xFFFFFFFFu, pos, 0);
                int rank = pos + __popc(bal & ((1u << lane) - 1u));
                if (k && rank < KCAP) g_kept[(size_t)img * KCAP + rank] = skey[t];
            }
            if (base + 32 >= m) break;
        }
    }

    // ---------- last block of this image runs the selection ----------
    __syncthreads();                         // all warps' pushes issued
    if (tid == 0) {
        __threadfence();                     // release g_kept/g_kcount writes
        int prev = atomicAdd(&g_done[img], 1);
        s_last = (prev == 9);
        if (prev == 9) g_done[img] = 0;      // self-clean for next replay
    }
    __syncthreads();
    if (!s_last) return;
    __threadfence();                         // acquire other blocks' writes

    int wid = ws;
    if (tid == 0) {                          // single-owner read + reset
        int k = g_kcount[img];
        g_kcount[img] = 0;
        skc = (k > KCAP) ? KCAP : k;
        sB = 0;
    }
    for (int i = tid; i < NBUCK; i += 256) hist[i] = 0;
    __syncthreads();                                              // BAR1
    int kc = skc;
    int need = (kc < DETN) ? kc : DETN;

    // scores in (0.96,1) -> fp32 sign/exponent fixed -> key order ==
    // (bucket = key bits [54:43], residual key) lexicographic, desc.
    const u64* kept = g_kept + (size_t)img * KCAP;
    for (int i = tid; i < kc; i += 256)
        atomicAdd(&hist[(unsigned)(kept[i] >> 43) & 0xFFFu], 1);
    __syncthreads();                                              // BAR2

    // thread owns 16 consecutive buckets
    int base = tid * 16;
    int c[16]; int csum = 0;
    #pragma unroll
    for (int j = 0; j < 16; j++) { c[j] = hist[base + j]; csum += c[j]; }

    int v = csum;                            // warp inclusive-suffix scan
    #pragma unroll
    for (int d = 1; d < 32; d <<= 1) {
        int u = __shfl_down_sync(0xFFFFFFFFu, v, d);
        if (lane + d < 32) v += u;
    }
    if (lane == 0) warp_sum[wid] = v;
    __syncthreads();                                              // BAR3
    if (tid < 8) {
        int s = 0;
        for (int w = tid + 1; w < 8; w++) s += warp_sum[w];
        warp_suf[tid] = s;
    }
    __syncthreads();                                              // BAR4

    // per-bucket exclusive-above offsets (into hist) + threshold bucket B*
    int run = (v - csum) + warp_suf[wid];
    #pragma unroll
    for (int j = 15; j >= 0; j--) {
        int excl = run;
        run += c[j];
        hist[base + j] = excl;
        if (need > 0 && run >= need && excl < need) sB = base + j;  // unique
    }
    __syncthreads();                                              // BAR5

    // scatter keys >= B* into per-bucket slots (disjoint ranges)
    int B = sB;
    for (int i = tid; i < kc; i += 256) {
        u64 key = kept[i];
        int h = (int)((unsigned)(key >> 43) & 0xFFFu);
        if (h >= B) {
            int p = atomicAdd(&hist[h], 1);
            if (p < 512) cand[p] = key;
        }
    }
    __syncthreads();                                              // BAR6

    // deterministic within-bucket order: tiny insertion sorts (desc)
    for (int h = tid; h < NBUCK; h += 256) {
        if (h >= B) {
            int hi = hist[h]; if (hi > 512) hi = 512;
            int lo = (h < NBUCK - 1) ? hist[h + 1] : 0;
            if (lo > 512) lo = 512;
            for (int a2 = lo + 1; a2 < hi; a2++) {
                u64 key = cand[a2];
                int b = a2;
                while (b > lo && cand[b - 1] < key) { cand[b] = cand[b - 1]; b--; }
                cand[b] = key;
            }
        }
    }
    __syncthreads();                                              // BAR7

    // decode + write top-300 (rows >= need zeroed)
    for (int r = tid; r < DETN; r += 256) {
        float o0 = 0.f, o1 = 0.f, o2 = 0.f, o3 = 0.f, o4 = 0.f, o5 = 0.f;
        if (r < need) {
            u64 key = cand[r];
            float sc = __uint_as_float((unsigned)(key >> 32));
            unsigned fi = 0xFFFFFFFFu - (unsigned)(key & 0xFFFFFFFFull);
            int anchor = (int)(fi / NCLS);
            int label  = (int)(fi - (unsigned)anchor * NCLS);
            const float* rr = pred + ((size_t)img * NA + anchor) * ROWL;
            float cx = __ldg(rr), cy = __ldg(rr + 1), w2 = __ldg(rr + 2), h2 = __ldg(rr + 3);
            float hw = __fmul_rn(0.5f, w2);
            float hv = __fmul_rn(0.5f, h2);
            o0 = __fsub_rn(cx, hw); o1 = __fsub_rn(cy, hv);
            o2 = __fadd_rn(cx, hw); o3 = __fadd_rn(cy, hv);
            o4 = sc; o5 = (float)label;
        }
        float* dst = out + ((size_t)img * DETN + r) * 6;
        dst[0] = o0; dst[1] = o1; dst[2] = o2;
        dst[3] = o3; dst[4] = o4; dst[5] = o5;
    }
}

// ---------------- launcher ----------------
extern "C" void kernel_launch(void* const* d_in, const int* in_sizes, int n_in,
                              void* d_out, int out_size) {
    const float* pred = (const float*)d_in[0];
    float* out = (float*)d_out;
    (void)in_sizes; (void)n_in; (void)out_size;

    k_extract<<<NA, 256>>>(pred);            // 25200 blocks, 1 warp/anchor (R6 proven)
    k_nms<<<80, 256>>>(pred, out);           // 8 classes/block + inline per-image top-300
}

// round 11
// speedup vs baseline: 1.2946x; 1.2946x over previous
#include <cuda_runtime.h>

#define NIMG 8
#define NA   25200
#define NCLS 80
#define ROWL 85
#define DETN 300
#define CONF 0.96f
#define IOUT 0.45f
#define BCAP 128            // per-(img,class) bucket capacity (E~20, sigma~4.5)
#define NBUCK 4096
#define SCAP 12             // per-(img,score-bucket) slot capacity (Poisson ~0.37)
#define NANCH (NIMG * NA)   // 201600
#define FBLK 19             // k_final blocks per image (8*19 = 152 >= 148)

typedef unsigned long long u64;

// ---------------- device scratch (zero-initialized at module load;
// g_ccount is reset by its consumer, g_bhist is re-zeroed by k_extract
// each launch, so every graph replay starts clean) -------------------------
__device__ int g_ccount[NIMG * NCLS];
__device__ u64 g_bucket[NIMG * NCLS * BCAP];
__device__ int g_bhist[NIMG * NBUCK];               // per-image score-bucket counts
__device__ u64 g_slot[(size_t)NIMG * NBUCK * SCAP]; // per-bucket kept keys

// ---------------- K1: extraction — one thread per anchor (measured-best
// shape: 788 blocks, 38% occ, 14.4us). Also zeroes g_bhist for this launch.
__global__ __launch_bounds__(256) void k_extract(const float* __restrict__ pred) {
    int tid  = threadIdx.x;
    int lane = tid & 31;
    int idx  = blockIdx.x * 256 + tid;

    // first 128 blocks zero the score-bucket histogram (32768 ints);
    // kernel boundary orders this before k_nms's writes.
    if (idx < NIMG * NBUCK) g_bhist[idx] = 0;

    bool valid = idx < NANCH;
    float obj = 0.f;
    if (valid) obj = __ldg(pred + (size_t)idx * ROWL + 4);

    unsigned hot = __ballot_sync(0xFFFFFFFFu, valid && obj > CONF);
    while (hot) {
        int src = __ffs(hot) - 1;
        hot &= hot - 1;
        int aidx = __shfl_sync(0xFFFFFFFFu, idx, src);
        float o  = __shfl_sync(0xFFFFFFFFu, obj, src);
        const float* r = pred + (size_t)aidx * ROWL;
        int img = aidx / NA;
        int a   = aidx - img * NA;
        #pragma unroll
        for (int base = 0; base < 96; base += 32) {
            int c = base + lane;
            if (c < NCLS) {
                float s = __fmul_rn(__ldg(r + 5 + c), o);
                if (s > CONF) {
                    unsigned fi = (unsigned)(a * NCLS + c);
                    u64 key = ((u64)__float_as_uint(s) << 32)
                              | (u64)(0xFFFFFFFFu - fi);
                    int slot = atomicAdd(&g_ccount[img * NCLS + c], 1);
                    if (slot < BCAP)
                        g_bucket[(size_t)(img * NCLS + c) * BCAP + slot] = key;
                }
            }
        }
    }
}

// ---------------- K2: per-(img,class) sort + greedy NMS — one warp each
// (proven 160x128 shape). Kept keys scatter straight into per-(img,bucket)
// global slots; no per-image kept list.
__global__ __launch_bounds__(128) void k_nms(const float* __restrict__ pred) {
    __shared__ u64    skey[4][BCAP];
    __shared__ float4 snb[4][BCAP];
    __shared__ float  sarea[4][BCAP];
    __shared__ unsigned char skeep[4][BCAP];

    int ws   = threadIdx.x >> 5;
    int lane = threadIdx.x & 31;
    int ww   = blockIdx.x * 4 + ws;          // (img, cls) id
    int img  = ww / NCLS;
    int cls  = ww - img * NCLS;

    int m = 0;
    if (lane == 0) {                         // single-owner read + reset
        m = g_ccount[ww];
        if (m > 0) g_ccount[ww] = 0;
    }
    m = __shfl_sync(0xFFFFFFFFu, m, 0);
    if (m > BCAP) m = BCAP;
    if (m == 0) return;

    const u64* bucket = g_bucket + (size_t)ww * BCAP;
    for (int t = lane; t < BCAP; t += 32)
        skey[ws][t] = (t < m) ? bucket[t] : 0ULL;
    __syncwarp();

    // bitonic sort desc over 128 unique keys (zeros sink to the tail)
    for (int k = 2; k <= BCAP; k <<= 1) {
        for (int j = k >> 1; j > 0; j >>= 1) {
            for (int t = lane; t < BCAP; t += 32) {
                int x = t ^ j;
                if (x > t) {
                    u64 va = skey[ws][t], vb = skey[ws][x];
                    bool up = ((t & k) == 0);
                    if ((va < vb) == up) { skey[ws][t] = vb; skey[ws][x] = va; }
                }
            }
            __syncwarp();
        }
    }

    // decode offset boxes + areas (exact reference fp expression order)
    float off = __fmul_rn((float)cls, 4.0f);
    for (int t = lane; t < m; t += 32) {
        unsigned fi = 0xFFFFFFFFu - (unsigned)(skey[ws][t] & 0xFFFFFFFFull);
        int anchor = (int)(fi / NCLS);
        const float* r = pred + ((size_t)img * NA + anchor) * ROWL;
        float cx = __ldg(r), cy = __ldg(r + 1), w2 = __ldg(r + 2), h2 = __ldg(r + 3);
        float hw = __fmul_rn(0.5f, w2);
        float hv = __fmul_rn(0.5f, h2);
        float4 nb;
        nb.x = __fadd_rn(__fsub_rn(cx, hw), off);
        nb.y = __fadd_rn(__fsub_rn(cy, hv), off);
        nb.z = __fadd_rn(__fadd_rn(cx, hw), off);
        nb.w = __fadd_rn(__fadd_rn(cy, hv), off);
        snb[ws][t]   = nb;
        sarea[ws][t] = __fmul_rn(__fsub_rn(nb.z, nb.x), __fsub_rn(nb.w, nb.y));
        skeep[ws][t] = 1;
    }
    __syncwarp();

    // greedy NMS in sorted order (== global sequential scan within class;
    // cross-class IoU is exactly 0 under the label*4 offset)
    for (int i = 0; i < m; i++) {
        if (skeep[ws][i]) {
            float4 bi = snb[ws][i];
            float  ai = sarea[ws][i];
            for (int t = i + 1 + lane; t < m; t += 32) {
                if (skeep[ws][t]) {
                    float4 bt = snb[ws][t];
                    float lx = fmaxf(bi.x, bt.x), ly = fmaxf(bi.y, bt.y);
                    float rx = fminf(bi.z, bt.z), ry = fminf(bi.w, bt.w);
                    float iw = fmaxf(__fsub_rn(rx, lx), 0.f);
                    float ih = fmaxf(__fsub_rn(ry, ly), 0.f);
                    float inter = __fmul_rn(iw, ih);
                    float den = __fadd_rn(
                        __fsub_rn(__fadd_rn(ai, sarea[ws][t]), inter), 1e-9f);
                    if (__fdiv_rn(inter, den) > IOUT) skeep[ws][t] = 0;
                }
            }
        }
        __syncwarp();
    }

    // scatter kept keys into per-(img, score-bucket) slots.
    // bucket = key bits [54:43] (top-12 score-mantissa bits; exponent is
    // fixed for scores in (0.96,1) so bucket order == score order).
    for (int t = lane; t < m; t += 32) {
        if (skeep[ws][t]) {
            u64 key = skey[ws][t];
            int h = (int)((unsigned)(key >> 43) & 0xFFFu);
            int slot = atomicAdd(&g_bhist[img * NBUCK + h], 1);
            if (slot < SCAP)
                g_slot[((size_t)(img * NBUCK + h)) * SCAP + slot] = key;
        }
    }
}

// ---------------- K3: rank resolution — 19 blocks per image (grid 152).
// Each block redundantly suffix-scans its image's 4096 bucket counts, then
// serves 16 output rows by binary-searching the rank's bucket and sorting
// that bucket's <=12 keys in registers (unique keys -> deterministic).
__global__ __launch_bounds__(256) void k_final(const float* __restrict__ pred,
                                               float* __restrict__ out) {
    __shared__ int sexcl[NBUCK];             // exclusive-above offsets, 16 KB
    __shared__ int warp_sum[8], warp_suf[8];
    __shared__ int s_total;

    int blk  = blockIdx.x;
    int img  = blk / FBLK;
    int sub  = blk - img * FBLK;
    int tid  = threadIdx.x;
    int wid  = tid >> 5;
    int lane = tid & 31;

    // load 16 bucket counts per thread + block-wide suffix scan (proven R9)
    const int* bh = g_bhist + img * NBUCK;
    int base = tid * 16;
    int c[16]; int csum = 0;
    #pragma unroll
    for (int j = 0; j < 16; j++) { c[j] = __ldg(bh + base + j); csum += c[j]; }

    int v = csum;                            // warp inclusive-suffix scan
    #pragma unroll
    for (int d = 1; d < 32; d <<= 1) {
        int u = __shfl_down_sync(0xFFFFFFFFu, v, d);
        if (lane + d < 32) v += u;
    }
    if (lane == 0) warp_sum[wid] = v;
    __syncthreads();
    if (tid < 8) {
        int s = 0;
        for (int w = tid + 1; w < 8; w++) s += warp_sum[w];
        warp_suf[tid] = s;
    }
    __syncthreads();

    int run = (v - csum) + warp_suf[wid];    // keys strictly above this chunk
    #pragma unroll
    for (int j = 15; j >= 0; j--) {
        int excl = run;
        run += c[j];
        sexcl[base + j] = excl;              // excl[h] = # keys in buckets > h
    }
    if (tid == 0) s_total = warp_suf[0] + warp_sum[0];
    __syncthreads();

    int total = s_total;
    int need = (total < DETN) ? total : DETN;

    // this block serves rows [sub*16, sub*16+16)
    if (tid < 16) {
        int r = sub * 16 + tid;
        if (r < DETN) {
            float o0 = 0.f, o1 = 0.f, o2 = 0.f, o3 = 0.f, o4 = 0.f, o5 = 0.f;
            if (r < need) {
                // smallest h with excl[h] <= r (excl non-increasing in h)
                int lo = 0, hi = NBUCK - 1;
                while (lo < hi) {
                    int mid = (lo + hi) >> 1;
                    if (sexcl[mid] <= r) hi = mid; else lo = mid + 1;
                }
                int h   = lo;
                int eh  = sexcl[h];
                int ehm = (h == 0) ? total : sexcl[h - 1];
                int cnt = ehm - eh; if (cnt > SCAP) cnt = SCAP;

                u64 keys[SCAP];
                const u64* sl = g_slot + ((size_t)(img * NBUCK + h)) * SCAP;
                for (int i = 0; i < cnt; i++) keys[i] = __ldg(sl + i);
                for (int a2 = 1; a2 < cnt; a2++) {   // insertion sort desc
                    u64 key = keys[a2];
                    int b = a2;
                    while (b > 0 && keys[b - 1] < key) { keys[b] = keys[b - 1]; b--; }
                    keys[b] = key;
                }
                int ridx = r - eh;
                if (ridx < cnt) {
                    u64 key = keys[ridx];
                    float sc = __uint_as_float((unsigned)(key >> 32));
                    unsigned fi = 0xFFFFFFFFu - (unsigned)(key & 0xFFFFFFFFull);
                    int anchor = (int)(fi / NCLS);
                    int label  = (int)(fi - (unsigned)anchor * NCLS);
                    const float* rr = pred + ((size_t)img * NA + anchor) * ROWL;
                    float cx = __ldg(rr),     cy = __ldg(rr + 1);
                    float w2 = __ldg(rr + 2), h2 = __ldg(rr + 3);
                    float hw = __fmul_rn(0.5f, w2);
                    float hv = __fmul_rn(0.5f, h2);
                    o0 = __fsub_rn(cx, hw); o1 = __fsub_rn(cy, hv);
                    o2 = __fadd_rn(cx, hw); o3 = __fadd_rn(cy, hv);
                    o4 = sc; o5 = (float)label;
                }
            }
            float* dst = out + ((size_t)img * DETN + r) * 6;
            dst[0] = o0; dst[1] = o1; dst[2] = o2;
            dst[3] = o3; dst[4] = o4; dst[5] = o5;
        }
    }
}

// ---------------- launcher ----------------
extern "C" void kernel_launch(void* const* d_in, const int* in_sizes, int n_in,
                              void* d_out, int out_size) {
    const float* pred = (const float*)d_in[0];
    float* out = (float*)d_out;
    (void)in_sizes; (void)n_in; (void)out_size;

    k_extract<<<(NANCH + 255) / 256, 256>>>(pred);   // 788 blocks (measured best)
    k_nms<<<(NIMG * NCLS) / 4, 128>>>(pred);         // 160 blocks, 1 warp/(img,cls)
    k_final<<<NIMG * FBLK, 256>>>(pred, out);        // 152 blocks, 16 rows each
}

// round 12
// speedup vs baseline: 1.3160x; 1.0165x over previous
#include <cuda_runtime.h>

#define NIMG 8
#define NA   25200
#define NCLS 80
#define ROWL 85
#define DETN 300
#define CONF 0.96f
#define IOUT 0.45f
#define BCAP 128            // per-(img,class) bucket capacity (E~20, sigma~4.5)
#define NBUCK 4096
#define SCAP 12             // per-(img,score-bucket) slot capacity (Poisson ~0.37)
#define NANCH (NIMG * NA)   // 201600
#define FBLK 19             // k_final blocks per image (8*19 = 152 >= 148)

typedef unsigned long long u64;

// ---------------- device scratch (zero-initialized at module load;
// g_ccount is reset by its consumer, g_bhist is re-zeroed by k_extract
// each launch, so every graph replay starts clean) -------------------------
__device__ int g_ccount[NIMG * NCLS];
__device__ u64 g_bucket[NIMG * NCLS * BCAP];
__device__ int g_bhist[NIMG * NBUCK];               // per-image score-bucket counts
__device__ u64 g_slot[(size_t)NIMG * NBUCK * SCAP]; // per-bucket kept keys

// ---------------- K1: extraction — one thread per anchor (measured best:
// 788 blocks, 14.4-14.9us). Also zeroes g_bhist for this launch.
__global__ __launch_bounds__(256) void k_extract(const float* __restrict__ pred) {
    int tid  = threadIdx.x;
    int lane = tid & 31;
    int idx  = blockIdx.x * 256 + tid;

    // first 128 blocks zero the score-bucket histogram (32768 ints);
    // kernel boundary orders this before k_nms's writes.
    if (idx < NIMG * NBUCK) g_bhist[idx] = 0;

    bool valid = idx < NANCH;
    float obj = 0.f;
    if (valid) obj = __ldg(pred + (size_t)idx * ROWL + 4);

    unsigned hot = __ballot_sync(0xFFFFFFFFu, valid && obj > CONF);
    while (hot) {
        int src = __ffs(hot) - 1;
        hot &= hot - 1;
        int aidx = __shfl_sync(0xFFFFFFFFu, idx, src);
        float o  = __shfl_sync(0xFFFFFFFFu, obj, src);
        const float* r = pred + (size_t)aidx * ROWL;
        int img = aidx / NA;
        int a   = aidx - img * NA;
        #pragma unroll
        for (int base = 0; base < 96; base += 32) {
            int c = base + lane;
            if (c < NCLS) {
                float s = __fmul_rn(__ldg(r + 5 + c), o);
                if (s > CONF) {
                    unsigned fi = (unsigned)(a * NCLS + c);
                    u64 key = ((u64)__float_as_uint(s) << 32)
                              | (u64)(0xFFFFFFFFu - fi);
                    int slot = atomicAdd(&g_ccount[img * NCLS + c], 1);
                    if (slot < BCAP)
                        g_bucket[(size_t)(img * NCLS + c) * BCAP + slot] = key;
                }
            }
        }
    }
}

// ---------------- K2: per-(img,class) sort + greedy NMS.
// One WARP = one BLOCK = one (img,cls): 640 single-warp blocks spread
// ~4.3/SM (beats 160x4-warp clumping at ~1.08 blocks/SM). Sort width is
// adaptive: n = next_pow2(max(32, m)) instead of always 128.
__global__ __launch_bounds__(32) void k_nms(const float* __restrict__ pred) {
    __shared__ u64    skey[BCAP];
    __shared__ float4 snb[BCAP];
    __shared__ float  sarea[BCAP];
    __shared__ unsigned char skeep[BCAP];

    int lane = threadIdx.x;
    int ww   = blockIdx.x;                   // (img, cls) id
    int img  = ww / NCLS;
    int cls  = ww - img * NCLS;

    int m = 0;
    if (lane == 0) {                         // single-owner read + reset
        m = g_ccount[ww];
        if (m > 0) g_ccount[ww] = 0;
    }
    m = __shfl_sync(0xFFFFFFFFu, m, 0);
    if (m > BCAP) m = BCAP;
    if (m == 0) return;

    int n = 32;                              // adaptive sort width
    while (n < m) n <<= 1;                   // 32 / 64 / 128

    const u64* bucket = g_bucket + (size_t)ww * BCAP;
    for (int t = lane; t < n; t += 32)
        skey[t] = (t < m) ? bucket[t] : 0ULL;
    __syncwarp();

    // bitonic sort desc over n unique keys (zeros sink to the tail)
    for (int k = 2; k <= n; k <<= 1) {
        for (int j = k >> 1; j > 0; j >>= 1) {
            for (int t = lane; t < n; t += 32) {
                int x = t ^ j;
                if (x > t) {
                    u64 va = skey[t], vb = skey[x];
                    bool up = ((t & k) == 0);
                    if ((va < vb) == up) { skey[t] = vb; skey[x] = va; }
                }
            }
            __syncwarp();
        }
    }

    // decode offset boxes + areas (exact reference fp expression order)
    float off = __fmul_rn((float)cls, 4.0f);
    for (int t = lane; t < m; t += 32) {
        unsigned fi = 0xFFFFFFFFu - (unsigned)(skey[t] & 0xFFFFFFFFull);
        int anchor = (int)(fi / NCLS);
        const float* r = pred + ((size_t)img * NA + anchor) * ROWL;
        float cx = __ldg(r), cy = __ldg(r + 1), w2 = __ldg(r + 2), h2 = __ldg(r + 3);
        float hw = __fmul_rn(0.5f, w2);
        float hv = __fmul_rn(0.5f, h2);
        float4 nb;
        nb.x = __fadd_rn(__fsub_rn(cx, hw), off);
        nb.y = __fadd_rn(__fsub_rn(cy, hv), off);
        nb.z = __fadd_rn(__fadd_rn(cx, hw), off);
        nb.w = __fadd_rn(__fadd_rn(cy, hv), off);
        snb[t]   = nb;
        sarea[t] = __fmul_rn(__fsub_rn(nb.z, nb.x), __fsub_rn(nb.w, nb.y));
        skeep[t] = 1;
    }
    __syncwarp();

    // greedy NMS in sorted order (== global sequential scan within class;
    // cross-class IoU is exactly 0 under the label*4 offset)
    for (int i = 0; i < m; i++) {
        if (skeep[i]) {
            float4 bi = snb[i];
            float  ai = sarea[i];
            for (int t = i + 1 + lane; t < m; t += 32) {
                if (skeep[t]) {
                    float4 bt = snb[t];
                    float lx = fmaxf(bi.x, bt.x), ly = fmaxf(bi.y, bt.y);
                    float rx = fminf(bi.z, bt.z), ry = fminf(bi.w, bt.w);
                    float iw = fmaxf(__fsub_rn(rx, lx), 0.f);
                    float ih = fmaxf(__fsub_rn(ry, ly), 0.f);
                    float inter = __fmul_rn(iw, ih);
                    float den = __fadd_rn(
                        __fsub_rn(__fadd_rn(ai, sarea[t]), inter), 1e-9f);
                    if (__fdiv_rn(inter, den) > IOUT) skeep[t] = 0;
                }
            }
        }
        __syncwarp();
    }

    // scatter kept keys into per-(img, score-bucket) slots.
    // bucket = key bits [54:43] (top-12 score-mantissa bits; exponent is
    // fixed for scores in (0.96,1) so bucket order == score order).
    for (int t = lane; t < m; t += 32) {
        if (skeep[t]) {
            u64 key = skey[t];
            int h = (int)((unsigned)(key >> 43) & 0xFFFu);
            int slot = atomicAdd(&g_bhist[img * NBUCK + h], 1);
            if (slot < SCAP)
                g_slot[((size_t)(img * NBUCK + h)) * SCAP + slot] = key;
        }
    }
}

// ---------------- K3: rank resolution — 19 blocks per image (grid 152).
// Each block redundantly suffix-scans its image's 4096 bucket counts, then
// serves 16 output rows by binary-searching the rank's bucket and sorting
// that bucket's <=12 keys in registers (unique keys -> deterministic).
__global__ __launch_bounds__(256) void k_final(const float* __restrict__ pred,
                                               float* __restrict__ out) {
    __shared__ int sexcl[NBUCK];             // exclusive-above offsets, 16 KB
    __shared__ int warp_sum[8], warp_suf[8];
    __shared__ int s_total;

    int blk  = blockIdx.x;
    int img  = blk / FBLK;
    int sub  = blk - img * FBLK;
    int tid  = threadIdx.x;
    int wid  = tid >> 5;
    int lane = tid & 31;

    // load 16 bucket counts per thread + block-wide suffix scan
    const int* bh = g_bhist + img * NBUCK;
    int base = tid * 16;
    int c[16]; int csum = 0;
    #pragma unroll
    for (int j = 0; j < 16; j++) { c[j] = __ldg(bh + base + j); csum += c[j]; }

    int v = csum;                            // warp inclusive-suffix scan
    #pragma unroll
    for (int d = 1; d < 32; d <<= 1) {
        int u = __shfl_down_sync(0xFFFFFFFFu, v, d);
        if (lane + d < 32) v += u;
    }
    if (lane == 0) warp_sum[wid] = v;
    __syncthreads();
    if (tid < 8) {
        int s = 0;
        for (int w = tid + 1; w < 8; w++) s += warp_sum[w];
        warp_suf[tid] = s;
    }
    __syncthreads();

    int run = (v - csum) + warp_suf[wid];    // keys strictly above this chunk
    #pragma unroll
    for (int j = 15; j >= 0; j--) {
        int excl = run;
        run += c[j];
        sexcl[base + j] = excl;              // excl[h] = # keys in buckets > h
    }
    if (tid == 0) s_total = warp_suf[0] + warp_sum[0];
    __syncthreads();

    int total = s_total;
    int need = (total < DETN) ? total : DETN;

    // this block serves rows [sub*16, sub*16+16)
    if (tid < 16) {
        int r = sub * 16 + tid;
        if (r < DETN) {
            float o0 = 0.f, o1 = 0.f, o2 = 0.f, o3 = 0.f, o4 = 0.f, o5 = 0.f;
            if (r < need) {
                // smallest h with excl[h] <= r (excl non-increasing in h)
                int lo = 0, hi = NBUCK - 1;
                while (lo < hi) {
                    int mid = (lo + hi) >> 1;
                    if (sexcl[mid] <= r) hi = mid; else lo = mid + 1;
                }
                int h   = lo;
                int eh  = sexcl[h];
                int ehm = (h == 0) ? total : sexcl[h - 1];
                int cnt = ehm - eh; if (cnt > SCAP) cnt = SCAP;

                u64 keys[SCAP];
                const u64* sl = g_slot + ((size_t)(img * NBUCK + h)) * SCAP;
                for (int i = 0; i < cnt; i++) keys[i] = __ldg(sl + i);
                for (int a2 = 1; a2 < cnt; a2++) {   // insertion sort desc
                    u64 key = keys[a2];
                    int b = a2;
                    while (b > 0 && keys[b - 1] < key) { keys[b] = keys[b - 1]; b--; }
                    keys[b] = key;
                }
                int ridx = r - eh;
                if (ridx < cnt) {
                    u64 key = keys[ridx];
                    float sc = __uint_as_float((unsigned)(key >> 32));
                    unsigned fi = 0xFFFFFFFFu - (unsigned)(key & 0xFFFFFFFFull);
                    int anchor = (int)(fi / NCLS);
                    int label  = (int)(fi - (unsigned)anchor * NCLS);
                    const float* rr = pred + ((size_t)img * NA + anchor) * ROWL;
                    float cx = __ldg(rr),     cy = __ldg(rr + 1);
                    float w2 = __ldg(rr + 2), h2 = __ldg(rr + 3);
                    float hw = __fmul_rn(0.5f, w2);
                    float hv = __fmul_rn(0.5f, h2);
                    o0 = __fsub_rn(cx, hw); o1 = __fsub_rn(cy, hv);
                    o2 = __fadd_rn(cx, hw); o3 = __fadd_rn(cy, hv);
                    o4 = sc; o5 = (float)label;
                }
            }
            float* dst = out + ((size_t)img * DETN + r) * 6;
            dst[0] = o0; dst[1] = o1; dst[2] = o2;
            dst[3] = o3; dst[4] = o4; dst[5] = o5;
        }
    }
}

// ---------------- launcher ----------------
extern "C" void kernel_launch(void* const* d_in, const int* in_sizes, int n_in,
                              void* d_out, int out_size) {
    const float* pred = (const float*)d_in[0];
    float* out = (float*)d_out;
    (void)in_sizes; (void)n_in; (void)out_size;

    k_extract<<<(NANCH + 255) / 256, 256>>>(pred);   // 788 blocks (measured best)
    k_nms<<<NIMG * NCLS, 32>>>(pred);                // 640 single-warp blocks
    k_final<<<NIMG * FBLK, 256>>>(pred, out);        // 152 blocks, 16 rows each
}

// round 13
// speedup vs baseline: 1.4028x; 1.0660x over previous
#include <cuda_runtime.h>

#define NIMG 8
#define NA   25200
#define NCLS 80
#define ROWL 85
#define DETN 300
#define CONF 0.96f
#define IOUT 0.45f
#define BCAP 128            // per-(img,class) bucket capacity (E~20, sigma~4.5)
#define NBUCK 4096
#define SCAP 12             // per-(img,score-bucket) slot capacity (Poisson ~0.37)
#define NANCH (NIMG * NA)   // 201600
#define FBLK 19             // k_final blocks per image (8*19 = 152 >= 148)

typedef unsigned long long u64;

// ---------------- device scratch (zero-initialized at module load;
// g_ccount is reset by its consumer, g_bhist is re-zeroed by k_extract
// each launch, so every graph replay starts clean) -------------------------
__device__ int g_ccount[NIMG * NCLS];
__device__ u64 g_bucket[NIMG * NCLS * BCAP];
__device__ int g_bhist[NIMG * NBUCK];               // per-image score-bucket counts
__device__ u64 g_slot[(size_t)NIMG * NBUCK * SCAP]; // per-bucket kept keys

// ---------------- K1: extraction — one thread per anchor, 128-thread
// blocks: grid 1575 ~= 10.6 blocks/SM ALL resident (regs=30 -> warp-limit
// 16 blocks/SM not binding) => ~2x the outstanding lines of the 788x256
// shape at identical traffic. Also zeroes g_bhist for this launch.
__global__ __launch_bounds__(128) void k_extract(const float* __restrict__ pred) {
    int tid  = threadIdx.x;
    int lane = tid & 31;
    int idx  = blockIdx.x * 128 + tid;

    // first 256 blocks zero the score-bucket histogram (32768 ints);
    // kernel boundary orders this before k_nms's writes.
    if (idx < NIMG * NBUCK) g_bhist[idx] = 0;

    bool valid = idx < NANCH;
    float obj = 0.f;
    if (valid) obj = __ldg(pred + (size_t)idx * ROWL + 4);

    unsigned hot = __ballot_sync(0xFFFFFFFFu, valid && obj > CONF);
    while (hot) {
        int src = __ffs(hot) - 1;
        hot &= hot - 1;
        int aidx = __shfl_sync(0xFFFFFFFFu, idx, src);
        float o  = __shfl_sync(0xFFFFFFFFu, obj, src);
        const float* r = pred + (size_t)aidx * ROWL;
        int img = aidx / NA;
        int a   = aidx - img * NA;
        #pragma unroll
        for (int base = 0; base < 96; base += 32) {
            int c = base + lane;
            if (c < NCLS) {
                float s = __fmul_rn(__ldg(r + 5 + c), o);
                if (s > CONF) {
                    unsigned fi = (unsigned)(a * NCLS + c);
                    u64 key = ((u64)__float_as_uint(s) << 32)
                              | (u64)(0xFFFFFFFFu - fi);
                    int slot = atomicAdd(&g_ccount[img * NCLS + c], 1);
                    if (slot < BCAP)
                        g_bucket[(size_t)(img * NCLS + c) * BCAP + slot] = key;
                }
            }
        }
    }
}

// ---------------- K2: per-(img,class) sort + greedy NMS.
// One WARP = one BLOCK = one (img,cls): 640 single-warp blocks.
// Sort width is adaptive: n = next_pow2(max(32, m)).
__global__ __launch_bounds__(32) void k_nms(const float* __restrict__ pred) {
    __shared__ u64    skey[BCAP];
    __shared__ float4 snb[BCAP];
    __shared__ float  sarea[BCAP];
    __shared__ unsigned char skeep[BCAP];

    int lane = threadIdx.x;
    int ww   = blockIdx.x;                   // (img, cls) id
    int img  = ww / NCLS;
    int cls  = ww - img * NCLS;

    int m = 0;
    if (lane == 0) {                         // single-owner read + reset
        m = g_ccount[ww];
        if (m > 0) g_ccount[ww] = 0;
    }
    m = __shfl_sync(0xFFFFFFFFu, m, 0);
    if (m > BCAP) m = BCAP;
    if (m == 0) return;

    int n = 32;                              // adaptive sort width
    while (n < m) n <<= 1;                   // 32 / 64 / 128

    const u64* bucket = g_bucket + (size_t)ww * BCAP;
    for (int t = lane; t < n; t += 32)
        skey[t] = (t < m) ? bucket[t] : 0ULL;
    __syncwarp();

    // bitonic sort desc over n unique keys (zeros sink to the tail)
    for (int k = 2; k <= n; k <<= 1) {
        for (int j = k >> 1; j > 0; j >>= 1) {
            for (int t = lane; t < n; t += 32) {
                int x = t ^ j;
                if (x > t) {
                    u64 va = skey[t], vb = skey[x];
                    bool up = ((t & k) == 0);
                    if ((va < vb) == up) { skey[t] = vb; skey[x] = va; }
                }
            }
            __syncwarp();
        }
    }

    // decode offset boxes + areas (exact reference fp expression order)
    float off = __fmul_rn((float)cls, 4.0f);
    for (int t = lane; t < m; t += 32) {
        unsigned fi = 0xFFFFFFFFu - (unsigned)(skey[t] & 0xFFFFFFFFull);
        int anchor = (int)(fi / NCLS);
        const float* r = pred + ((size_t)img * NA + anchor) * ROWL;
        float cx = __ldg(r), cy = __ldg(r + 1), w2 = __ldg(r + 2), h2 = __ldg(r + 3);
        float hw = __fmul_rn(0.5f, w2);
        float hv = __fmul_rn(0.5f, h2);
        float4 nb;
        nb.x = __fadd_rn(__fsub_rn(cx, hw), off);
        nb.y = __fadd_rn(__fsub_rn(cy, hv), off);
        nb.z = __fadd_rn(__fadd_rn(cx, hw), off);
        nb.w = __fadd_rn(__fadd_rn(cy, hv), off);
        snb[t]   = nb;
        sarea[t] = __fmul_rn(__fsub_rn(nb.z, nb.x), __fsub_rn(nb.w, nb.y));
        skeep[t] = 1;
    }
    __syncwarp();

    // greedy NMS in sorted order (== global sequential scan within class;
    // cross-class IoU is exactly 0 under the label*4 offset)
    for (int i = 0; i < m; i++) {
        if (skeep[i]) {
            float4 bi = snb[i];
            float  ai = sarea[i];
            for (int t = i + 1 + lane; t < m; t += 32) {
                if (skeep[t]) {
                    float4 bt = snb[t];
                    float lx = fmaxf(bi.x, bt.x), ly = fmaxf(bi.y, bt.y);
                    float rx = fminf(bi.z, bt.z), ry = fminf(bi.w, bt.w);
                    float iw = fmaxf(__fsub_rn(rx, lx), 0.f);
                    float ih = fmaxf(__fsub_rn(ry, ly), 0.f);
                    float inter = __fmul_rn(iw, ih);
                    float den = __fadd_rn(
                        __fsub_rn(__fadd_rn(ai, sarea[t]), inter), 1e-9f);
                    if (__fdiv_rn(inter, den) > IOUT) skeep[t] = 0;
                }
            }
        }
        __syncwarp();
    }

    // scatter kept keys into per-(img, score-bucket) slots.
    // bucket = key bits [54:43] (top-12 score-mantissa bits; exponent is
    // fixed for scores in (0.96,1) so bucket order == score order).
    for (int t = lane; t < m; t += 32) {
        if (skeep[t]) {
            u64 key = skey[t];
            int h = (int)((unsigned)(key >> 43) & 0xFFFu);
            int slot = atomicAdd(&g_bhist[img * NBUCK + h], 1);
            if (slot < SCAP)
                g_slot[((size_t)(img * NBUCK + h)) * SCAP + slot] = key;
        }
    }
}

// ---------------- K3: rank resolution — 19 blocks per image (grid 152).
// Each block redundantly suffix-scans its image's 4096 bucket counts, then
// serves 16 output rows by binary-searching the rank's bucket and sorting
// that bucket's <=12 keys in registers (unique keys -> deterministic).
__global__ __launch_bounds__(256) void k_final(const float* __restrict__ pred,
                                               float* __restrict__ out) {
    __shared__ int sexcl[NBUCK];             // exclusive-above offsets, 16 KB
    __shared__ int warp_sum[8], warp_suf[8];
    __shared__ int s_total;

    int blk  = blockIdx.x;
    int img  = blk / FBLK;
    int sub  = blk - img * FBLK;
    int tid  = threadIdx.x;
    int wid  = tid >> 5;
    int lane = tid & 31;

    // load 16 bucket counts per thread + block-wide suffix scan
    const int* bh = g_bhist + img * NBUCK;
    int base = tid * 16;
    int c[16]; int csum = 0;
    #pragma unroll
    for (int j = 0; j < 16; j++) { c[j] = __ldg(bh + base + j); csum += c[j]; }

    int v = csum;                            // warp inclusive-suffix scan
    #pragma unroll
    for (int d = 1; d < 32; d <<= 1) {
        int u = __shfl_down_sync(0xFFFFFFFFu, v, d);
        if (lane + d < 32) v += u;
    }
    if (lane == 0) warp_sum[wid] = v;
    __syncthreads();
    if (tid < 8) {
        int s = 0;
        for (int w = tid + 1; w < 8; w++) s += warp_sum[w];
        warp_suf[tid] = s;
    }
    __syncthreads();

    int run = (v - csum) + warp_suf[wid];    // keys strictly above this chunk
    #pragma unroll
    for (int j = 15; j >= 0; j--) {
        int excl = run;
        run += c[j];
        sexcl[base + j] = excl;              // excl[h] = # keys in buckets > h
    }
    if (tid == 0) s_total = warp_suf[0] + warp_sum[0];
    __syncthreads();

    int total = s_total;
    int need = (total < DETN) ? total : DETN;

    // this block serves rows [sub*16, sub*16+16)
    if (tid < 16) {
        int r = sub * 16 + tid;
        if (r < DETN) {
            float o0 = 0.f, o1 = 0.f, o2 = 0.f, o3 = 0.f, o4 = 0.f, o5 = 0.f;
            if (r < need) {
                // smallest h with excl[h] <= r (excl non-increasing in h)
                int lo = 0, hi = NBUCK - 1;
                while (lo < hi) {
                    int mid = (lo + hi) >> 1;
                    if (sexcl[mid] <= r) hi = mid; else lo = mid + 1;
                }
                int h   = lo;
                int eh  = sexcl[h];
                int ehm = (h == 0) ? total : sexcl[h - 1];
                int cnt = ehm - eh; if (cnt > SCAP) cnt = SCAP;

                u64 keys[SCAP];
                const u64* sl = g_slot + ((size_t)(img * NBUCK + h)) * SCAP;
                for (int i = 0; i < cnt; i++) keys[i] = __ldg(sl + i);
                for (int a2 = 1; a2 < cnt; a2++) {   // insertion sort desc
                    u64 key = keys[a2];
                    int b = a2;
                    while (b > 0 && keys[b - 1] < key) { keys[b] = keys[b - 1]; b--; }
                    keys[b] = key;
                }
                int ridx = r - eh;
                if (ridx < cnt) {
                    u64 key = keys[ridx];
                    float sc = __uint_as_float((unsigned)(key >> 32));
                    unsigned fi = 0xFFFFFFFFu - (unsigned)(key & 0xFFFFFFFFull);
                    int anchor = (int)(fi / NCLS);
                    int label  = (int)(fi - (unsigned)anchor * NCLS);
                    const float* rr = pred + ((size_t)img * NA + anchor) * ROWL;
                    float cx = __ldg(rr),     cy = __ldg(rr + 1);
                    float w2 = __ldg(rr + 2), h2 = __ldg(rr + 3);
                    float hw = __fmul_rn(0.5f, w2);
                    float hv = __fmul_rn(0.5f, h2);
                    o0 = __fsub_rn(cx, hw); o1 = __fsub_rn(cy, hv);
                    o2 = __fadd_rn(cx, hw); o3 = __fadd_rn(cy, hv);
                    o4 = sc; o5 = (float)label;
                }
            }
            float* dst = out + ((size_t)img * DETN + r) * 6;
            dst[0] = o0; dst[1] = o1; dst[2] = o2;
            dst[3] = o3; dst[4] = o4; dst[5] = o5;
        }
    }
}

// ---------------- launcher ----------------
extern "C" void kernel_launch(void* const* d_in, const int* in_sizes, int n_in,
                              void* d_out, int out_size) {
    const float* pred = (const float*)d_in[0];
    float* out = (float*)d_out;
    (void)in_sizes; (void)n_in; (void)out_size;

    k_extract<<<NANCH / 128, 128>>>(pred);           // 1575 blocks, all resident
    k_nms<<<NIMG * NCLS, 32>>>(pred);                // 640 single-warp blocks
    k_final<<<NIMG * FBLK, 256>>>(pred, out);        // 152 blocks, 16 rows each
}

// round 15
// speedup vs baseline: 1.4318x; 1.0206x over previous
#include <cuda_runtime.h>
#include <cstdint>

#define NIMG 8
#define NA   25200
#define NCLS 80
#define ROWL 85
#define DETN 300
#define CONF 0.96f
#define IOUT 0.45f
#define BCAP 128            // per-(img,class) bucket capacity (E~20, sigma~4.5)
#define NBUCK 4096
#define SCAP 12             // per-(img,score-bucket) slot capacity (Poisson ~0.37)
#define NANCH (NIMG * NA)   // 201600
#define FBLK 19             // k_final blocks per image (8*19 = 152 >= 148)

#define EBLKS 296           // k_extract blocks (exactly 2 per SM)
#define ETHR  256
#define ESTR  (EBLKS * ETHR)    // 75776: anchor stride per slot
#define HOTCAP 128          // per-block hot-anchor list (E~31, sigma~5.4)

typedef unsigned long long u64;

// ---------------- device scratch (zero-initialized at module load;
// g_ccount is reset by its consumer, g_bhist is re-zeroed by k_extract
// each launch, so every graph replay starts clean) -------------------------
__device__ int g_ccount[NIMG * NCLS];
__device__ u64 g_bucket[NIMG * NCLS * BCAP];
__device__ int g_bhist[NIMG * NBUCK];               // per-image score-bucket counts
__device__ u64 g_slot[(size_t)NIMG * NBUCK * SCAP]; // per-bucket kept keys

// ---------------- K1: extraction, cp.async deep-pipelined scan.
// Phase A: each thread cp.asyncs up to 3 obj values (stride ESTR) into smem
// BEFORE any wait -> ~200k lines in flight chip-wide -> scan runs at LTS
// service rate, not at (resident-warps x 1-line) latency rate.
// Phase B: hot anchors (block-shared list) processed by 8 warps with
// double-buffered row prefetch.
__global__ __launch_bounds__(ETHR) void k_extract(const float* __restrict__ pred) {
    __shared__ float sobj[3 * ETHR];
    __shared__ u64   s_hot[HOTCAP];
    __shared__ int   s_hotn;

    int tid  = threadIdx.x;
    int lane = tid & 31;
    int wid  = tid >> 5;
    int g    = blockIdx.x * ETHR + tid;

    if (tid == 0) s_hotn = 0;

    // zero score-bucket histogram (32768 ints; 75776 threads cover it);
    // kernel boundary orders this before k_nms's writes.
    if (g < NIMG * NBUCK) g_bhist[g] = 0;

    // ---- phase A: issue all obj fetches, then wait once ----
    #pragma unroll
    for (int i = 0; i < 3; i++) {
        int a = g + i * ESTR;
        if (a < NANCH) {
            unsigned int sa =
                (unsigned int)__cvta_generic_to_shared(&sobj[i * ETHR + tid]);
            const float* gp = pred + (size_t)a * ROWL + 4;
            asm volatile("cp.async.ca.shared.global [%0], [%1], 4;"
                         :: "r"(sa), "l"(gp));
        } else {
            sobj[i * ETHR + tid] = 0.f;
        }
    }
    asm volatile("cp.async.commit_group;");
    __syncthreads();                         // s_hotn=0 visible
    asm volatile("cp.async.wait_group 0;" ::: "memory");

    // ---- hot detection + block-shared push (warp-aggregated) ----
    #pragma unroll
    for (int i = 0; i < 3; i++) {
        int a = g + i * ESTR;
        float obj = sobj[i * ETHR + tid];
        bool hot = (a < NANCH) && (obj > CONF);
        unsigned bal = __ballot_sync(0xFFFFFFFFu, hot);
        int cnt = __popc(bal);
        if (cnt) {
            int pos = 0;
            if (lane == 0) pos = atomicAdd(&s_hotn, cnt);
            pos = __shfl_sync(0xFFFFFFFFu, pos, 0);
            int rank = pos + __popc(bal & ((1u << lane) - 1u));
            if (hot && rank < HOTCAP)
                s_hot[rank] = ((u64)__float_as_uint(obj) << 32) | (u64)a;
        }
    }
    __syncthreads();

    // ---- phase B: warps process hot rows, double-buffered prefetch ----
    int nh = s_hotn; if (nh > HOTCAP) nh = HOTCAP;
    int h = wid;
    float c0 = 0.f, c1 = 0.f, c2 = 0.f;      // classes lane, lane+32, lane+64
    int aidx = 0; float o = 0.f;
    if (h < nh) {
        u64 e = s_hot[h];
        aidx = (int)(e & 0xFFFFFFFFull);
        o    = __uint_as_float((unsigned)(e >> 32));
        const float* r = pred + (size_t)aidx * ROWL;
        c0 = __ldg(r + 5 + lane);
        c1 = __ldg(r + 37 + lane);
        c2 = (lane < 16) ? __ldg(r + 69 + lane) : 0.f;
    }
    while (h < nh) {
        // prefetch next row before processing current
        int h2 = h + 8;
        float n0 = 0.f, n1 = 0.f, n2 = 0.f;
        int na = 0; float no = 0.f;
        if (h2 < nh) {
            u64 e = s_hot[h2];
            na = (int)(e & 0xFFFFFFFFull);
            no = __uint_as_float((unsigned)(e >> 32));
            const float* r = pred + (size_t)na * ROWL;
            n0 = __ldg(r + 5 + lane);
            n1 = __ldg(r + 37 + lane);
            n2 = (lane < 16) ? __ldg(r + 69 + lane) : 0.f;
        }
        // process current row (exact reference fp expression order)
        {
            int img = aidx / NA;
            int a   = aidx - img * NA;
            #pragma unroll
            for (int q = 0; q < 3; q++) {
                int c = lane + 32 * q;
                float cv = (q == 0) ? c0 : (q == 1) ? c1 : c2;
                if (c < NCLS) {
                    float s = __fmul_rn(cv, o);
                    if (s > CONF) {
                        unsigned fi = (unsigned)(a * NCLS + c);
                        u64 key = ((u64)__float_as_uint(s) << 32)
                                  | (u64)(0xFFFFFFFFu - fi);
                        int slot = atomicAdd(&g_ccount[img * NCLS + c], 1);
                        if (slot < BCAP)
                            g_bucket[(size_t)(img * NCLS + c) * BCAP + slot] = key;
                    }
                }
            }
        }
        c0 = n0; c1 = n1; c2 = n2; aidx = na; o = no; h = h2;
    }
}

// ---------------- K2: per-(img,class) sort + greedy NMS.
// One WARP = one BLOCK = one (img,cls): 640 single-warp blocks.
// Sort width is adaptive: n = next_pow2(max(32, m)).
__global__ __launch_bounds__(32) void k_nms(const float* __restrict__ pred) {
    __shared__ u64    skey[BCAP];
    __shared__ float4 snb[BCAP];
    __shared__ float  sarea[BCAP];
    __shared__ unsigned char skeep[BCAP];

    int lane = threadIdx.x;
    int ww   = blockIdx.x;                   // (img, cls) id
    int img  = ww / NCLS;
    int cls  = ww - img * NCLS;

    int m = 0;
    if (lane == 0) {                         // single-owner read + reset
        m = g_ccount[ww];
        if (m > 0) g_ccount[ww] = 0;
    }
    m = __shfl_sync(0xFFFFFFFFu, m, 0);
    if (m > BCAP) m = BCAP;
    if (m == 0) return;

    int n = 32;                              // adaptive sort width
    while (n < m) n <<= 1;                   // 32 / 64 / 128

    const u64* bucket = g_bucket + (size_t)ww * BCAP;
    for (int t = lane; t < n; t += 32)
        skey[t] = (t < m) ? bucket[t] : 0ULL;
    __syncwarp();

    // bitonic sort desc over n unique keys (zeros sink to the tail)
    for (int k = 2; k <= n; k <<= 1) {
        for (int j = k >> 1; j > 0; j >>= 1) {
            for (int t = lane; t < n; t += 32) {
                int x = t ^ j;
                if (x > t) {
                    u64 va = skey[t], vb = skey[x];
                    bool up = ((t & k) == 0);
                    if ((va < vb) == up) { skey[t] = vb; skey[x] = va; }
                }
            }
            __syncwarp();
        }
    }

    // decode offset boxes + areas (exact reference fp expression order)
    float off = __fmul_rn((float)cls, 4.0f);
    for (int t = lane; t < m; t += 32) {
        unsigned fi = 0xFFFFFFFFu - (unsigned)(skey[t] & 0xFFFFFFFFull);
        int anchor = (int)(fi / NCLS);
        const float* r = pred + ((size_t)img * NA + anchor) * ROWL;
        float cx = __ldg(r), cy = __ldg(r + 1), w2 = __ldg(r + 2), h2 = __ldg(r + 3);
        float hw = __fmul_rn(0.5f, w2);
        float hv = __fmul_rn(0.5f, h2);
        float4 nb;
        nb.x = __fadd_rn(__fsub_rn(cx, hw), off);
        nb.y = __fadd_rn(__fsub_rn(cy, hv), off);
        nb.z = __fadd_rn(__fadd_rn(cx, hw), off);
        nb.w = __fadd_rn(__fadd_rn(cy, hv), off);
        snb[t]   = nb;
        sarea[t] = __fmul_rn(__fsub_rn(nb.z, nb.x), __fsub_rn(nb.w, nb.y));
        skeep[t] = 1;
    }
    __syncwarp();

    // greedy NMS in sorted order (== global sequential scan within class;
    // cross-class IoU is exactly 0 under the label*4 offset)
    for (int i = 0; i < m; i++) {
        if (skeep[i]) {
            float4 bi = snb[i];
            float  ai = sarea[i];
            for (int t = i + 1 + lane; t < m; t += 32) {
                if (skeep[t]) {
                    float4 bt = snb[t];
                    float lx = fmaxf(bi.x, bt.x), ly = fmaxf(bi.y, bt.y);
                    float rx = fminf(bi.z, bt.z), ry = fminf(bi.w, bt.w);
                    float iw = fmaxf(__fsub_rn(rx, lx), 0.f);
                    float ih = fmaxf(__fsub_rn(ry, ly), 0.f);
                    float inter = __fmul_rn(iw, ih);
                    float den = __fadd_rn(
                        __fsub_rn(__fadd_rn(ai, sarea[t]), inter), 1e-9f);
                    if (__fdiv_rn(inter, den) > IOUT) skeep[t] = 0;
                }
            }
        }
        __syncwarp();
    }

    // scatter kept keys into per-(img, score-bucket) slots.
    // bucket = key bits [54:43] (top-12 score-mantissa bits; exponent is
    // fixed for scores in (0.96,1) so bucket order == score order).
    for (int t = lane; t < m; t += 32) {
        if (skeep[t]) {
            u64 key = skey[t];
            int h = (int)((unsigned)(key >> 43) & 0xFFFu);
            int slot = atomicAdd(&g_bhist[img * NBUCK + h], 1);
            if (slot < SCAP)
                g_slot[((size_t)(img * NBUCK + h)) * SCAP + slot] = key;
        }
    }
}

// ---------------- K3: rank resolution — 19 blocks per image (grid 152).
// Each block redundantly suffix-scans its image's 4096 bucket counts, then
// serves 16 output rows by binary-searching the rank's bucket and sorting
// that bucket's <=12 keys in registers (unique keys -> deterministic).
__global__ __launch_bounds__(256) void k_final(const float* __restrict__ pred,
                                               float* __restrict__ out) {
    __shared__ int sexcl[NBUCK];             // exclusive-above offsets, 16 KB
    __shared__ int warp_sum[8], warp_suf[8];
    __shared__ int s_total;

    int blk  = blockIdx.x;
    int img  = blk / FBLK;
    int sub  = blk - img * FBLK;
    int tid  = threadIdx.x;
    int wid  = tid >> 5;
    int lane = tid & 31;

    // load 16 bucket counts per thread + block-wide suffix scan
    const int* bh = g_bhist + img * NBUCK;
    int base = tid * 16;
    int c[16]; int csum = 0;
    #pragma unroll
    for (int j = 0; j < 16; j++) { c[j] = __ldg(bh + base + j); csum += c[j]; }

    int v = csum;                            // warp inclusive-suffix scan
    #pragma unroll
    for (int d = 1; d < 32; d <<= 1) {
        int u = __shfl_down_sync(0xFFFFFFFFu, v, d);
        if (lane + d < 32) v += u;
    }
    if (lane == 0) warp_sum[wid] = v;
    __syncthreads();
    if (tid < 8) {
        int s = 0;
        for (int w = tid + 1; w < 8; w++) s += warp_sum[w];
        warp_suf[tid] = s;
    }
    __syncthreads();

    int run = (v - csum) + warp_suf[wid];    // keys strictly above this chunk
    #pragma unroll
    for (int j = 15; j >= 0; j--) {
        int excl = run;
        run += c[j];
        sexcl[base + j] = excl;              // excl[h] = # keys in buckets > h
    }
    if (tid == 0) s_total = warp_suf[0] + warp_sum[0];
    __syncthreads();

    int total = s_total;
    int need = (total < DETN) ? total : DETN;

    // this block serves rows [sub*16, sub*16+16)
    if (tid < 16) {
        int r = sub * 16 + tid;
        if (r < DETN) {
            float o0 = 0.f, o1 = 0.f, o2 = 0.f, o3 = 0.f, o4 = 0.f, o5 = 0.f;
            if (r < need) {
                // smallest h with excl[h] <= r (excl non-increasing in h)
                int lo = 0, hi = NBUCK - 1;
                while (lo < hi) {
                    int mid = (lo + hi) >> 1;
                    if (sexcl[mid] <= r) hi = mid; else lo = mid + 1;
                }
                int h   = lo;
                int eh  = sexcl[h];
                int ehm = (h == 0) ? total : sexcl[h - 1];
                int cnt = ehm - eh; if (cnt > SCAP) cnt = SCAP;

                u64 keys[SCAP];
                const u64* sl = g_slot + ((size_t)(img * NBUCK + h)) * SCAP;
                for (int i = 0; i < cnt; i++) keys[i] = __ldg(sl + i);
                for (int a2 = 1; a2 < cnt; a2++) {   // insertion sort desc
                    u64 key = keys[a2];
                    int b = a2;
                    while (b > 0 && keys[b - 1] < key) { keys[b] = keys[b - 1]; b--; }
                    keys[b] = key;
                }
                int ridx = r - eh;
                if (ridx < cnt) {
                    u64 key = keys[ridx];
                    float sc = __uint_as_float((unsigned)(key >> 32));
                    unsigned fi = 0xFFFFFFFFu - (unsigned)(key & 0xFFFFFFFFull);
                    int anchor = (int)(fi / NCLS);
                    int label  = (int)(fi - (unsigned)anchor * NCLS);
                    const float* rr = pred + ((size_t)img * NA + anchor) * ROWL;
                    float cx = __ldg(rr),     cy = __ldg(rr + 1);
                    float w2 = __ldg(rr + 2), h2 = __ldg(rr + 3);
                    float hw = __fmul_rn(0.5f, w2);
                    float hv = __fmul_rn(0.5f, h2);
                    o0 = __fsub_rn(cx, hw); o1 = __fsub_rn(cy, hv);
                    o2 = __fadd_rn(cx, hw); o3 = __fadd_rn(cy, hv);
                    o4 = sc; o5 = (float)label;
                }
            }
            float* dst = out + ((size_t)img * DETN + r) * 6;
            dst[0] = o0; dst[1] = o1; dst[2] = o2;
            dst[3] = o3; dst[4] = o4; dst[5] = o5;
        }
    }
}

// ---------------- launcher ----------------
extern "C" void kernel_launch(void* const* d_in, const int* in_sizes, int n_in,
                              void* d_out, int out_size) {
    const float* pred = (const float*)d_in[0];
    float* out = (float*)d_out;
    (void)in_sizes; (void)n_in; (void)out_size;

    k_extract<<<EBLKS, ETHR>>>(pred);                // 296 blocks, cp.async scan
    k_nms<<<NIMG * NCLS, 32>>>(pred);                // 640 single-warp blocks
    k_final<<<NIMG * FBLK, 256>>>(pred, out);        // 152 blocks, 16 rows each
}